// round 2
// baseline (speedup 1.0000x reference)
#include <cuda_runtime.h>
#include <math.h>

// Problem constants
#define NB     32
#define NS     4096
#define ND     2048
#define DH     128
#define LUTN   4096
#define NSPLIT 8
#define SCHUNK (NS / NSPLIT)   // 512

// fp32 constants matching the reference computation
#define PHI_F   1.6180340f                 // (1+sqrt(5))/2 rounded to fp32
#define CONST_C 651.89865f                 // 4096 / (2*pi)
#define STEP_F  0.0015339808f              // (2*pi) / 4096

// Device scratch (no allocations allowed in kernel_launch)
static __device__ float2 g_lut[LUTN];         // (cos, sin) per LUT index
static __device__ float2 g_q[NB * DH];        // (cos_q, sin_q)
static __device__ float  g_rk[DH];            // 1 / (1 + |w_key|)
static __device__ float  g_scores[NB * NS];
static __device__ float  g_partial[NSPLIT * NB * ND];

// ---------------------------------------------------------------------------
// Kernel A: build LUT, key reciprocals, and the query cos/sin vectors
// grid: 32 x 256 = 8192 threads
// ---------------------------------------------------------------------------
__global__ void init_kernel(const float* __restrict__ x,
                            const float* __restrict__ t,
                            const float* __restrict__ wq,
                            const float* __restrict__ bq,
                            const float* __restrict__ wk)
{
    int i = blockIdx.x * blockDim.x + threadIdx.x;
    if (i < LUTN) {
        float ang = (float)i * STEP_F;
        g_lut[i] = make_float2(cosf(ang), sinf(ang));
    }
    if (i < DH) {
        g_rk[i] = 1.0f / (1.0f + fabsf(wk[i]));
    }
    int j = i - LUTN;
    if (j >= 0 && j < NB * DH) {
        int b = j >> 7;
        int d = j & (DH - 1);
        float rq    = 1.0f / (1.0f + fabsf(wq[d]));
        float theta = x[b * ND + d] * rq + bq[d] + t[b] * PHI_F;
        int idx = __float2int_rd(theta * CONST_C) & (LUTN - 1);
        float ang = (float)idx * STEP_F;
        g_q[j] = make_float2(cosf(ang), sinf(ang));
    }
}

// ---------------------------------------------------------------------------
// Kernel B: scores[b,s] = (1/16) * sum_d cosq*cosk + sinq*sink
// grid: (NS/64, NB), block 256 (8 warps, each warp does 8 rows)
// ---------------------------------------------------------------------------
__global__ void scores_kernel(const float* __restrict__ cs,
                              const float* __restrict__ bk)
{
    __shared__ float2 slut[LUTN];
    int tid = threadIdx.x;
    #pragma unroll
    for (int k = 0; k < LUTN / 256; k++)
        slut[tid + k * 256] = g_lut[tid + k * 256];
    __syncthreads();

    int b    = blockIdx.y;
    int warp = tid >> 5;
    int lane = tid & 31;

    // lane owns d = 4*lane .. 4*lane+3
    float4 rk4 = *(const float4*)(g_rk + 4 * lane);
    float4 bk4 = *(const float4*)(bk + 4 * lane);
    float2 q0 = g_q[b * DH + 4 * lane + 0];
    float2 q1 = g_q[b * DH + 4 * lane + 1];
    float2 q2 = g_q[b * DH + 4 * lane + 2];
    float2 q3 = g_q[b * DH + 4 * lane + 3];

    const float* base = cs + (size_t)b * NS * ND;
    int s0 = blockIdx.x * 64 + warp * 8;

    #pragma unroll
    for (int r = 0; r < 8; r++) {
        int s = s0 + r;
        float4 v = *(const float4*)(base + (size_t)s * ND + 4 * lane);
        float part = 0.0f;
        {
            float th = fmaf(v.x, rk4.x, bk4.x);
            float2 sc = slut[__float2int_rd(th * CONST_C) & (LUTN - 1)];
            part = fmaf(q0.x, sc.x, part); part = fmaf(q0.y, sc.y, part);
        }
        {
            float th = fmaf(v.y, rk4.y, bk4.y);
            float2 sc = slut[__float2int_rd(th * CONST_C) & (LUTN - 1)];
            part = fmaf(q1.x, sc.x, part); part = fmaf(q1.y, sc.y, part);
        }
        {
            float th = fmaf(v.z, rk4.z, bk4.z);
            float2 sc = slut[__float2int_rd(th * CONST_C) & (LUTN - 1)];
            part = fmaf(q2.x, sc.x, part); part = fmaf(q2.y, sc.y, part);
        }
        {
            float th = fmaf(v.w, rk4.w, bk4.w);
            float2 sc = slut[__float2int_rd(th * CONST_C) & (LUTN - 1)];
            part = fmaf(q3.x, sc.x, part); part = fmaf(q3.y, sc.y, part);
        }
        #pragma unroll
        for (int o = 16; o > 0; o >>= 1)
            part += __shfl_xor_sync(0xFFFFFFFFu, part, o);
        if (lane == 0)
            g_scores[b * NS + s] = part * 0.0625f;  // / sqrt(2*128) = /16
    }
}

// ---------------------------------------------------------------------------
// Kernel C: softmax over S per batch; writes weights straight into d_out
// grid: NB blocks, 512 threads, 8 elements/thread
// ---------------------------------------------------------------------------
__global__ void softmax_kernel(float* __restrict__ wout)
{
    int b   = blockIdx.x;
    int tid = threadIdx.x;
    __shared__ float red[16];

    float v[8];
    float mx = -1e30f;
    #pragma unroll
    for (int j = 0; j < 8; j++) {
        v[j] = g_scores[b * NS + tid + j * 512];
        mx = fmaxf(mx, v[j]);
    }
    // block max reduce
    #pragma unroll
    for (int o = 16; o > 0; o >>= 1)
        mx = fmaxf(mx, __shfl_xor_sync(0xFFFFFFFFu, mx, o));
    if ((tid & 31) == 0) red[tid >> 5] = mx;
    __syncthreads();
    if (tid < 32) {
        float m = (tid < 16) ? red[tid] : -1e30f;
        #pragma unroll
        for (int o = 8; o > 0; o >>= 1)
            m = fmaxf(m, __shfl_xor_sync(0xFFFFFFFFu, m, o));
        if (tid == 0) red[0] = m;
    }
    __syncthreads();
    mx = red[0];

    float sum = 0.0f;
    #pragma unroll
    for (int j = 0; j < 8; j++) {
        v[j] = expf(v[j] - mx);
        sum += v[j];
    }
    __syncthreads();  // reuse red[]
    #pragma unroll
    for (int o = 16; o > 0; o >>= 1)
        sum += __shfl_xor_sync(0xFFFFFFFFu, sum, o);
    if ((tid & 31) == 0) red[tid >> 5] = sum;
    __syncthreads();
    if (tid < 32) {
        float s = (tid < 16) ? red[tid] : 0.0f;
        #pragma unroll
        for (int o = 8; o > 0; o >>= 1)
            s += __shfl_xor_sync(0xFFFFFFFFu, s, o);
        if (tid == 0) red[0] = s;
    }
    __syncthreads();
    float inv = 1.0f / red[0];

    #pragma unroll
    for (int j = 0; j < 8; j++)
        wout[b * NS + tid + j * 512] = v[j] * inv;
}

// ---------------------------------------------------------------------------
// Kernel D: partial[b,d] (per s-split) = sum_{s in chunk} w[b,s] * cs[b,s,d]
// grid: (4 d-tiles, NSPLIT s-chunks, NB batches), block 128 (thread = float4)
// ---------------------------------------------------------------------------
__global__ void out_partial_kernel(const float* __restrict__ cs,
                                   const float* __restrict__ wts)
{
    int dt  = blockIdx.x;     // 0..3, 512 floats each
    int sc  = blockIdx.y;     // 0..NSPLIT-1
    int b   = blockIdx.z;
    int tid = threadIdx.x;    // 0..127

    __shared__ float ws[SCHUNK];
    #pragma unroll
    for (int k = 0; k < SCHUNK / 128; k++)
        ws[tid + k * 128] = wts[b * NS + sc * SCHUNK + tid + k * 128];
    __syncthreads();

    const float4* p = (const float4*)(cs + ((size_t)(b * NS + sc * SCHUNK)) * ND
                                         + dt * 512) + tid;
    float4 acc = make_float4(0.f, 0.f, 0.f, 0.f);
    #pragma unroll 8
    for (int s = 0; s < SCHUNK; s++) {
        float w  = ws[s];
        float4 v = p[(size_t)s * (ND / 4)];
        acc.x = fmaf(w, v.x, acc.x);
        acc.y = fmaf(w, v.y, acc.y);
        acc.z = fmaf(w, v.z, acc.z);
        acc.w = fmaf(w, v.w, acc.w);
    }
    float* dst = g_partial + ((size_t)(sc * NB + b)) * ND + dt * 512 + tid * 4;
    *(float4*)dst = acc;
}

// ---------------------------------------------------------------------------
// Kernel E: deterministic reduction of the NSPLIT partials into d_out
// ---------------------------------------------------------------------------
__global__ void out_reduce_kernel(float* __restrict__ out)
{
    int i = blockIdx.x * blockDim.x + threadIdx.x;  // 0..NB*ND-1
    float s = 0.0f;
    #pragma unroll
    for (int c = 0; c < NSPLIT; c++)
        s += g_partial[(size_t)c * NB * ND + i];
    out[i] = s;
}

// ---------------------------------------------------------------------------
extern "C" void kernel_launch(void* const* d_in, const int* in_sizes, int n_in,
                              void* d_out, int out_size)
{
    const float* x  = (const float*)d_in[0];   // (32, 2048)
    const float* cs = (const float*)d_in[1];   // (32, 4096, 2048)
    const float* t  = (const float*)d_in[2];   // (32,)
    const float* wq = (const float*)d_in[3];   // (128,)
    const float* bq = (const float*)d_in[4];   // (128,)
    const float* wk = (const float*)d_in[5];   // (128,)
    const float* bk = (const float*)d_in[6];   // (128,)

    float* out_main = (float*)d_out;            // (32, 2048)
    float* out_wts  = out_main + NB * ND;       // (32, 4096)

    init_kernel<<<32, 256>>>(x, t, wq, bq, wk);

    dim3 gS(NS / 64, NB);
    scores_kernel<<<gS, 256>>>(cs, bk);

    softmax_kernel<<<NB, 512>>>(out_wts);

    dim3 gO(4, NSPLIT, NB);
    out_partial_kernel<<<gO, 128>>>(cs, out_wts);

    out_reduce_kernel<<<(NB * ND) / 256, 256>>>(out_main);
}

// round 4
// speedup vs baseline: 1.0671x; 1.0671x over previous
#include <cuda_runtime.h>
#include <math.h>

// Problem constants
#define NB     32
#define NS     4096
#define ND     2048
#define DH     128
#define LUTN   4096
#define NSPLIT 16
#define SCHUNK (NS / NSPLIT)   // 256

// fp32 constants matching the reference computation
#define PHI_F   1.6180340f                 // (1+sqrt(5))/2 rounded to fp32
#define CONST_C 651.89865f                 // 4096 / (2*pi)
#define STEP_F  0.0015339808f              // (2*pi) / 4096

// Device scratch (no allocations allowed in kernel_launch)
static __device__ float2 g_q[NB * DH];        // (cos_q, sin_q)
static __device__ float  g_rk[DH];            // 1 / (1 + |w_key|)
static __device__ float  g_scores[NB * NS];
static __device__ float  g_partial[NSPLIT * NB * ND];

// ---------------------------------------------------------------------------
// Kernel A: key reciprocals and the query cos/sin vectors
// ---------------------------------------------------------------------------
__global__ void init_kernel(const float* __restrict__ x,
                            const float* __restrict__ t,
                            const float* __restrict__ wq,
                            const float* __restrict__ bq,
                            const float* __restrict__ wk)
{
    int i = blockIdx.x * blockDim.x + threadIdx.x;
    if (i < DH) {
        g_rk[i] = 1.0f / (1.0f + fabsf(wk[i]));
    }
    if (i < NB * DH) {
        int b = i >> 7;
        int d = i & (DH - 1);
        float rq    = 1.0f / (1.0f + fabsf(wq[d]));
        float theta = x[b * ND + d] * rq + bq[d] + t[b] * PHI_F;
        int idx = __float2int_rd(theta * CONST_C) & (LUTN - 1);
        float ang = (float)idx * STEP_F;
        g_q[i] = make_float2(cosf(ang), sinf(ang));
    }
}

// ---------------------------------------------------------------------------
// Kernel B: scores[b,s] = (1/16) * sum_d cosq*cosk + sinq*sink
// Quantized-angle cos/sin computed with MUFU (__sincosf) — no LUT traffic.
// grid: (NS/64, NB), block 256 (8 warps, each warp does 8 rows)
// ---------------------------------------------------------------------------
__device__ __forceinline__ float dot_term(float v, float rk, float bk,
                                          float2 q)
{
    float th  = fmaf(v, rk, bk);
    int  idx  = __float2int_rd(th * CONST_C) & (LUTN - 1);
    float ang = (float)idx * STEP_F;
    float sn, cn;
    __sincosf(ang, &sn, &cn);
    return fmaf(q.x, cn, q.y * sn);
}

__global__ void scores_kernel(const float* __restrict__ cs,
                              const float* __restrict__ bk)
{
    int tid  = threadIdx.x;
    int b    = blockIdx.y;
    int warp = tid >> 5;
    int lane = tid & 31;

    // lane owns d = 4*lane .. 4*lane+3
    float4 rk4 = *(const float4*)(g_rk + 4 * lane);
    float4 bk4 = *(const float4*)(bk + 4 * lane);
    float2 q0 = g_q[b * DH + 4 * lane + 0];
    float2 q1 = g_q[b * DH + 4 * lane + 1];
    float2 q2 = g_q[b * DH + 4 * lane + 2];
    float2 q3 = g_q[b * DH + 4 * lane + 3];

    const float* base = cs + (size_t)b * NS * ND;
    int s0 = blockIdx.x * 64 + warp * 8;

    #pragma unroll
    for (int r = 0; r < 8; r++) {
        int s = s0 + r;
        float4 v = __ldcs((const float4*)(base + (size_t)s * ND + 4 * lane));
        float part = dot_term(v.x, rk4.x, bk4.x, q0);
        part      += dot_term(v.y, rk4.y, bk4.y, q1);
        part      += dot_term(v.z, rk4.z, bk4.z, q2);
        part      += dot_term(v.w, rk4.w, bk4.w, q3);
        #pragma unroll
        for (int o = 16; o > 0; o >>= 1)
            part += __shfl_xor_sync(0xFFFFFFFFu, part, o);
        if (lane == 0)
            g_scores[b * NS + s] = part * 0.0625f;  // / sqrt(2*128) = /16
    }
}

// ---------------------------------------------------------------------------
// Kernel C: softmax over S per batch; writes weights straight into d_out
// grid: NB blocks, 512 threads, 8 elements/thread
// ---------------------------------------------------------------------------
__global__ void softmax_kernel(float* __restrict__ wout)
{
    int b   = blockIdx.x;
    int tid = threadIdx.x;
    __shared__ float red[16];

    float v[8];
    float mx = -1e30f;
    #pragma unroll
    for (int j = 0; j < 8; j++) {
        v[j] = g_scores[b * NS + tid + j * 512];
        mx = fmaxf(mx, v[j]);
    }
    #pragma unroll
    for (int o = 16; o > 0; o >>= 1)
        mx = fmaxf(mx, __shfl_xor_sync(0xFFFFFFFFu, mx, o));
    if ((tid & 31) == 0) red[tid >> 5] = mx;
    __syncthreads();
    if (tid < 32) {
        float m = (tid < 16) ? red[tid] : -1e30f;
        #pragma unroll
        for (int o = 8; o > 0; o >>= 1)
            m = fmaxf(m, __shfl_xor_sync(0xFFFFFFFFu, m, o));
        if (tid == 0) red[0] = m;
    }
    __syncthreads();
    mx = red[0];

    float sum = 0.0f;
    #pragma unroll
    for (int j = 0; j < 8; j++) {
        v[j] = expf(v[j] - mx);
        sum += v[j];
    }
    __syncthreads();
    #pragma unroll
    for (int o = 16; o > 0; o >>= 1)
        sum += __shfl_xor_sync(0xFFFFFFFFu, sum, o);
    if ((tid & 31) == 0) red[tid >> 5] = sum;
    __syncthreads();
    if (tid < 32) {
        float s = (tid < 16) ? red[tid] : 0.0f;
        #pragma unroll
        for (int o = 8; o > 0; o >>= 1)
            s += __shfl_xor_sync(0xFFFFFFFFu, s, o);
        if (tid == 0) red[0] = s;
    }
    __syncthreads();
    float inv = 1.0f / red[0];

    #pragma unroll
    for (int j = 0; j < 8; j++)
        wout[b * NS + tid + j * 512] = v[j] * inv;
}

// ---------------------------------------------------------------------------
// Kernel D: partial[b,d] (per s-split) = sum_{s in chunk} w[b,s] * cs[b,s,d]
// grid: (4 d-tiles, NSPLIT s-chunks, NB batches), block 128 (thread = float4)
// 2048 blocks -> ~14 resident blocks/SM -> high occupancy / MLP
// ---------------------------------------------------------------------------
__global__ void out_partial_kernel(const float* __restrict__ cs,
                                   const float* __restrict__ wts)
{
    int dt  = blockIdx.x;     // 0..3, 512 floats each
    int sc  = blockIdx.y;     // 0..NSPLIT-1
    int b   = blockIdx.z;
    int tid = threadIdx.x;    // 0..127

    __shared__ float ws[SCHUNK];
    #pragma unroll
    for (int k = 0; k < SCHUNK / 128; k++)
        ws[tid + k * 128] = wts[b * NS + sc * SCHUNK + tid + k * 128];
    __syncthreads();

    const float4* p = (const float4*)(cs + ((size_t)(b * NS + sc * SCHUNK)) * ND
                                         + dt * 512) + tid;
    float4 acc = make_float4(0.f, 0.f, 0.f, 0.f);
    #pragma unroll 8
    for (int s = 0; s < SCHUNK; s++) {
        float w  = ws[s];
        float4 v = __ldcs(p + (size_t)s * (ND / 4));
        acc.x = fmaf(w, v.x, acc.x);
        acc.y = fmaf(w, v.y, acc.y);
        acc.z = fmaf(w, v.z, acc.z);
        acc.w = fmaf(w, v.w, acc.w);
    }
    float* dst = g_partial + ((size_t)(sc * NB + b)) * ND + dt * 512 + tid * 4;
    *(float4*)dst = acc;
}

// ---------------------------------------------------------------------------
// Kernel E: deterministic reduction of the NSPLIT partials into d_out
// ---------------------------------------------------------------------------
__global__ void out_reduce_kernel(float* __restrict__ out)
{
    int i = blockIdx.x * blockDim.x + threadIdx.x;  // 0..NB*ND-1
    float s = 0.0f;
    #pragma unroll
    for (int c = 0; c < NSPLIT; c++)
        s += g_partial[(size_t)c * NB * ND + i];
    out[i] = s;
}

// ---------------------------------------------------------------------------
extern "C" void kernel_launch(void* const* d_in, const int* in_sizes, int n_in,
                              void* d_out, int out_size)
{
    const float* x  = (const float*)d_in[0];   // (32, 2048)
    const float* cs = (const float*)d_in[1];   // (32, 4096, 2048)
    const float* t  = (const float*)d_in[2];   // (32,)
    const float* wq = (const float*)d_in[3];   // (128,)
    const float* bq = (const float*)d_in[4];   // (128,)
    const float* wk = (const float*)d_in[5];   // (128,)
    const float* bk = (const float*)d_in[6];   // (128,)

    float* out_main = (float*)d_out;            // (32, 2048)
    float* out_wts  = out_main + NB * ND;       // (32, 4096)

    init_kernel<<<16, 256>>>(x, t, wq, bq, wk);

    dim3 gS(NS / 64, NB);
    scores_kernel<<<gS, 256>>>(cs, bk);

    softmax_kernel<<<NB, 512>>>(out_wts);

    dim3 gO(4, NSPLIT, NB);
    out_partial_kernel<<<gO, 128>>>(cs, out_wts);

    out_reduce_kernel<<<(NB * ND) / 256, 256>>>(out_main);
}

// round 5
// speedup vs baseline: 1.1231x; 1.0525x over previous
#include <cuda_runtime.h>
#include <math.h>

// Problem constants
#define NB     32
#define NS     4096
#define ND     2048
#define DH     128
#define LUTN   4096
#define NSPLIT 16
#define SCHUNK (NS / NSPLIT)   // 256

// fp32 constants matching the reference computation
#define PHI_F   1.6180340f                 // (1+sqrt(5))/2 rounded to fp32
#define CONST_C 651.89865f                 // 4096 / (2*pi)
#define STEP_F  0.0015339808f              // (2*pi) / 4096

// Device scratch (no allocations allowed in kernel_launch)
static __device__ float  g_scores[NB * NS];
static __device__ float  g_partial[NSPLIT * NB * ND];

// ---------------------------------------------------------------------------
// Quantized-angle cos/sin term (matches LUT reference to ~1e-6)
// ---------------------------------------------------------------------------
__device__ __forceinline__ float2 qsincos(float theta)
{
    int  idx  = __float2int_rd(theta * CONST_C) & (LUTN - 1);
    float ang = (float)idx * STEP_F;
    float sn, cn;
    __sincosf(ang, &sn, &cn);
    return make_float2(cn, sn);
}

__device__ __forceinline__ float dot_term(float v, float rk, float bk,
                                          float2 q)
{
    float2 sc = qsincos(fmaf(v, rk, bk));
    return fmaf(q.x, sc.x, q.y * sc.y);
}

// ---------------------------------------------------------------------------
// Kernel B: scores[b,s] = (1/16) * sum_d cosq*cosk + sinq*sink
// Per-block recompute of the tiny q/rk setup (no init kernel needed).
// Loads use DEFAULT caching so the 64 MB head-patch stays in L2 for
// out_partial to re-hit.
// grid: (NS/64, NB), block 256 (8 warps, each warp does 8 rows)
// ---------------------------------------------------------------------------
__global__ void scores_kernel(const float* __restrict__ cs,
                              const float* __restrict__ x,
                              const float* __restrict__ t,
                              const float* __restrict__ wq,
                              const float* __restrict__ bq,
                              const float* __restrict__ wk,
                              const float* __restrict__ bk)
{
    int tid  = threadIdx.x;
    int b    = blockIdx.y;
    int warp = tid >> 5;
    int lane = tid & 31;

    // lane owns d = 4*lane .. 4*lane+3 : compute rk, bk, and q locally
    float4 wk4 = *(const float4*)(wk + 4 * lane);
    float4 bk4 = *(const float4*)(bk + 4 * lane);
    float4 rk4 = make_float4(1.0f / (1.0f + fabsf(wk4.x)),
                             1.0f / (1.0f + fabsf(wk4.y)),
                             1.0f / (1.0f + fabsf(wk4.z)),
                             1.0f / (1.0f + fabsf(wk4.w)));

    float4 wq4 = *(const float4*)(wq + 4 * lane);
    float4 bq4 = *(const float4*)(bq + 4 * lane);
    float4 xq  = *(const float4*)(x + (size_t)b * ND + 4 * lane);
    float  tb  = t[b] * PHI_F;

    float2 q0 = qsincos(fmaf(xq.x, 1.0f / (1.0f + fabsf(wq4.x)), bq4.x + tb));
    float2 q1 = qsincos(fmaf(xq.y, 1.0f / (1.0f + fabsf(wq4.y)), bq4.y + tb));
    float2 q2 = qsincos(fmaf(xq.z, 1.0f / (1.0f + fabsf(wq4.z)), bq4.z + tb));
    float2 q3 = qsincos(fmaf(xq.w, 1.0f / (1.0f + fabsf(wq4.w)), bq4.w + tb));

    const float* base = cs + (size_t)b * NS * ND;
    int s0 = blockIdx.x * 64 + warp * 8;

    #pragma unroll
    for (int r = 0; r < 8; r++) {
        int s = s0 + r;
        // default caching: seed L2 with the head patch for out_partial
        float4 v = *(const float4*)(base + (size_t)s * ND + 4 * lane);
        float part = dot_term(v.x, rk4.x, bk4.x, q0);
        part      += dot_term(v.y, rk4.y, bk4.y, q1);
        part      += dot_term(v.z, rk4.z, bk4.z, q2);
        part      += dot_term(v.w, rk4.w, bk4.w, q3);
        #pragma unroll
        for (int o = 16; o > 0; o >>= 1)
            part += __shfl_xor_sync(0xFFFFFFFFu, part, o);
        if (lane == 0)
            g_scores[b * NS + s] = part * 0.0625f;  // / sqrt(2*128) = /16
    }
}

// ---------------------------------------------------------------------------
// Kernel C: softmax over S per batch; writes weights straight into d_out
// grid: NB blocks, 512 threads, 8 elements/thread
// ---------------------------------------------------------------------------
__global__ void softmax_kernel(float* __restrict__ wout)
{
    int b   = blockIdx.x;
    int tid = threadIdx.x;
    __shared__ float red[16];

    float v[8];
    float mx = -1e30f;
    #pragma unroll
    for (int j = 0; j < 8; j++) {
        v[j] = g_scores[b * NS + tid + j * 512];
        mx = fmaxf(mx, v[j]);
    }
    #pragma unroll
    for (int o = 16; o > 0; o >>= 1)
        mx = fmaxf(mx, __shfl_xor_sync(0xFFFFFFFFu, mx, o));
    if ((tid & 31) == 0) red[tid >> 5] = mx;
    __syncthreads();
    if (tid < 32) {
        float m = (tid < 16) ? red[tid] : -1e30f;
        #pragma unroll
        for (int o = 8; o > 0; o >>= 1)
            m = fmaxf(m, __shfl_xor_sync(0xFFFFFFFFu, m, o));
        if (tid == 0) red[0] = m;
    }
    __syncthreads();
    mx = red[0];

    float sum = 0.0f;
    #pragma unroll
    for (int j = 0; j < 8; j++) {
        v[j] = expf(v[j] - mx);
        sum += v[j];
    }
    __syncthreads();
    #pragma unroll
    for (int o = 16; o > 0; o >>= 1)
        sum += __shfl_xor_sync(0xFFFFFFFFu, sum, o);
    if ((tid & 31) == 0) red[tid >> 5] = sum;
    __syncthreads();
    if (tid < 32) {
        float s = (tid < 16) ? red[tid] : 0.0f;
        #pragma unroll
        for (int o = 8; o > 0; o >>= 1)
            s += __shfl_xor_sync(0xFFFFFFFFu, s, o);
        if (tid == 0) red[0] = s;
    }
    __syncthreads();
    float inv = 1.0f / red[0];

    #pragma unroll
    for (int j = 0; j < 8; j++)
        wout[b * NS + tid + j * 512] = v[j] * inv;
}

// ---------------------------------------------------------------------------
// Kernel D: partial[b,d] (per s-split) = sum_{s in chunk} w[b,s] * cs[b,s,d]
// grid: (4 d-tiles, NSPLIT s-chunks, NB batches), block 128 (thread = float4)
// __ldcs: evict-first streaming — its own lines self-evict, preserving the
// scores-seeded head-patch lines in L2 (which dt=0 blocks re-hit).
// ---------------------------------------------------------------------------
__global__ void out_partial_kernel(const float* __restrict__ cs,
                                   const float* __restrict__ wts)
{
    int dt  = blockIdx.x;     // 0..3, 512 floats each
    int sc  = blockIdx.y;     // 0..NSPLIT-1
    int b   = blockIdx.z;
    int tid = threadIdx.x;    // 0..127

    __shared__ float ws[SCHUNK];
    #pragma unroll
    for (int k = 0; k < SCHUNK / 128; k++)
        ws[tid + k * 128] = wts[b * NS + sc * SCHUNK + tid + k * 128];
    __syncthreads();

    const float4* p = (const float4*)(cs + ((size_t)(b * NS + sc * SCHUNK)) * ND
                                         + dt * 512) + tid;
    float4 acc = make_float4(0.f, 0.f, 0.f, 0.f);
    #pragma unroll 8
    for (int s = 0; s < SCHUNK; s++) {
        float w  = ws[s];
        float4 v = __ldcs(p + (size_t)s * (ND / 4));
        acc.x = fmaf(w, v.x, acc.x);
        acc.y = fmaf(w, v.y, acc.y);
        acc.z = fmaf(w, v.z, acc.z);
        acc.w = fmaf(w, v.w, acc.w);
    }
    float* dst = g_partial + ((size_t)(sc * NB + b)) * ND + dt * 512 + tid * 4;
    *(float4*)dst = acc;
}

// ---------------------------------------------------------------------------
// Kernel E: deterministic reduction of the NSPLIT partials into d_out
// ---------------------------------------------------------------------------
__global__ void out_reduce_kernel(float* __restrict__ out)
{
    int i = blockIdx.x * blockDim.x + threadIdx.x;  // 0..NB*ND-1
    float s = 0.0f;
    #pragma unroll
    for (int c = 0; c < NSPLIT; c++)
        s += g_partial[(size_t)c * NB * ND + i];
    out[i] = s;
}

// ---------------------------------------------------------------------------
extern "C" void kernel_launch(void* const* d_in, const int* in_sizes, int n_in,
                              void* d_out, int out_size)
{
    const float* x  = (const float*)d_in[0];   // (32, 2048)
    const float* cs = (const float*)d_in[1];   // (32, 4096, 2048)
    const float* t  = (const float*)d_in[2];   // (32,)
    const float* wq = (const float*)d_in[3];   // (128,)
    const float* bq = (const float*)d_in[4];   // (128,)
    const float* wk = (const float*)d_in[5];   // (128,)
    const float* bk = (const float*)d_in[6];   // (128,)

    float* out_main = (float*)d_out;            // (32, 2048)
    float* out_wts  = out_main + NB * ND;       // (32, 4096)

    dim3 gS(NS / 64, NB);
    scores_kernel<<<gS, 256>>>(cs, x, t, wq, bq, wk, bk);

    softmax_kernel<<<NB, 512>>>(out_wts);

    dim3 gO(4, NSPLIT, NB);
    out_partial_kernel<<<gO, 128>>>(cs, out_wts);

    out_reduce_kernel<<<(NB * ND) / 256, 256>>>(out_main);
}

// round 7
// speedup vs baseline: 1.1475x; 1.0217x over previous
#include <cuda_runtime.h>
#include <math.h>

// Problem constants
#define NB     32
#define NS     4096
#define ND     2048
#define DH     128
#define LUTN   4096
#define NSPLIT 16
#define SCHUNK (NS / NSPLIT)   // 256

// fp32 constants matching the reference computation
#define PHI_F   1.6180340f                 // (1+sqrt(5))/2 rounded to fp32
#define CONST_C 651.89865f                 // 4096 / (2*pi)
#define STEP_F  0.0015339808f              // (2*pi) / 4096

// Device scratch (no allocations allowed in kernel_launch)
static __device__ float  g_scores[NB * NS];
static __device__ float  g_partial[NSPLIT * NB * ND];

// ---------------------------------------------------------------------------
// Quantized angle index (identical to reference LUT indexing)
// ---------------------------------------------------------------------------
__device__ __forceinline__ int qidx(float theta)
{
    return __float2int_rd(theta * CONST_C) & (LUTN - 1);
}

// cos(thq)cos(thk) + sin(thq)sin(thk) = cos((idx_q - idx_k) * STEP)
// exact identity on the quantized grid (4096*STEP = 2*pi)
__device__ __forceinline__ float dot_term(float v, float rk, float bk, int iq)
{
    int ik = qidx(fmaf(v, rk, bk));
    return __cosf((float)(iq - ik) * STEP_F);
}

// ---------------------------------------------------------------------------
// Kernel B: scores[b,s] = (1/16) * sum_d cos(theta_q - theta_k) [quantized]
// Loads use DEFAULT caching so the 64 MB head-patch stays in L2 for
// out_partial to re-hit.
// grid: (NS/64, NB), block 256 (8 warps, each warp does 8 rows)
// ---------------------------------------------------------------------------
__global__ void scores_kernel(const float* __restrict__ cs,
                              const float* __restrict__ x,
                              const float* __restrict__ t,
                              const float* __restrict__ wq,
                              const float* __restrict__ bq,
                              const float* __restrict__ wk,
                              const float* __restrict__ bk)
{
    int tid  = threadIdx.x;
    int b    = blockIdx.y;
    int warp = tid >> 5;
    int lane = tid & 31;

    // lane owns d = 4*lane .. 4*lane+3 : compute rk, bk, and q indices locally
    float4 wk4 = *(const float4*)(wk + 4 * lane);
    float4 bk4 = *(const float4*)(bk + 4 * lane);
    float4 rk4 = make_float4(1.0f / (1.0f + fabsf(wk4.x)),
                             1.0f / (1.0f + fabsf(wk4.y)),
                             1.0f / (1.0f + fabsf(wk4.z)),
                             1.0f / (1.0f + fabsf(wk4.w)));

    float4 wq4 = *(const float4*)(wq + 4 * lane);
    float4 bq4 = *(const float4*)(bq + 4 * lane);
    float4 xq  = *(const float4*)(x + (size_t)b * ND + 4 * lane);
    float  tb  = t[b] * PHI_F;

    int iq0 = qidx(fmaf(xq.x, 1.0f / (1.0f + fabsf(wq4.x)), bq4.x + tb));
    int iq1 = qidx(fmaf(xq.y, 1.0f / (1.0f + fabsf(wq4.y)), bq4.y + tb));
    int iq2 = qidx(fmaf(xq.z, 1.0f / (1.0f + fabsf(wq4.z)), bq4.z + tb));
    int iq3 = qidx(fmaf(xq.w, 1.0f / (1.0f + fabsf(wq4.w)), bq4.w + tb));

    const float* base = cs + (size_t)b * NS * ND;
    int s0 = blockIdx.x * 64 + warp * 8;

    #pragma unroll
    for (int r = 0; r < 8; r++) {
        int s = s0 + r;
        // default caching: seed L2 with the head patch for out_partial
        float4 v = *(const float4*)(base + (size_t)s * ND + 4 * lane);
        float part = dot_term(v.x, rk4.x, bk4.x, iq0);
        part      += dot_term(v.y, rk4.y, bk4.y, iq1);
        part      += dot_term(v.z, rk4.z, bk4.z, iq2);
        part      += dot_term(v.w, rk4.w, bk4.w, iq3);
        #pragma unroll
        for (int o = 16; o > 0; o >>= 1)
            part += __shfl_xor_sync(0xFFFFFFFFu, part, o);
        if (lane == 0)
            g_scores[b * NS + s] = part * 0.0625f;  // / sqrt(2*128) = /16
    }
}

// ---------------------------------------------------------------------------
// Kernel C: softmax over S per batch; writes weights straight into d_out
// grid: NB blocks, 512 threads, 8 elements/thread
// ---------------------------------------------------------------------------
__global__ void softmax_kernel(float* __restrict__ wout)
{
    int b   = blockIdx.x;
    int tid = threadIdx.x;
    __shared__ float red[16];

    float v[8];
    float mx = -1e30f;
    #pragma unroll
    for (int j = 0; j < 8; j++) {
        v[j] = g_scores[b * NS + tid + j * 512];
        mx = fmaxf(mx, v[j]);
    }
    #pragma unroll
    for (int o = 16; o > 0; o >>= 1)
        mx = fmaxf(mx, __shfl_xor_sync(0xFFFFFFFFu, mx, o));
    if ((tid & 31) == 0) red[tid >> 5] = mx;
    __syncthreads();
    if (tid < 32) {
        float m = (tid < 16) ? red[tid] : -1e30f;
        #pragma unroll
        for (int o = 8; o > 0; o >>= 1)
            m = fmaxf(m, __shfl_xor_sync(0xFFFFFFFFu, m, o));
        if (tid == 0) red[0] = m;
    }
    __syncthreads();
    mx = red[0];

    float sum = 0.0f;
    #pragma unroll
    for (int j = 0; j < 8; j++) {
        v[j] = __expf(v[j] - mx);
        sum += v[j];
    }
    __syncthreads();
    #pragma unroll
    for (int o = 16; o > 0; o >>= 1)
        sum += __shfl_xor_sync(0xFFFFFFFFu, sum, o);
    if ((tid & 31) == 0) red[tid >> 5] = sum;
    __syncthreads();
    if (tid < 32) {
        float s = (tid < 16) ? red[tid] : 0.0f;
        #pragma unroll
        for (int o = 8; o > 0; o >>= 1)
            s += __shfl_xor_sync(0xFFFFFFFFu, s, o);
        if (tid == 0) red[0] = s;
    }
    __syncthreads();
    float inv = 1.0f / red[0];

    #pragma unroll
    for (int j = 0; j < 8; j++)
        wout[b * NS + tid + j * 512] = v[j] * inv;
}

// ---------------------------------------------------------------------------
// Kernel D: partial[b,d] (per s-split) = sum_{s in chunk} w[b,s] * cs[b,s,d]
// grid: (4 d-tiles, NSPLIT s-chunks, NB batches), block 128 (thread = float4)
// __ldcs: evict-first streaming — its own lines self-evict, preserving the
// scores-seeded head-patch lines in L2 (which dt=0 blocks re-hit).
// ---------------------------------------------------------------------------
__global__ void out_partial_kernel(const float* __restrict__ cs,
                                   const float* __restrict__ wts)
{
    int dt  = blockIdx.x;     // 0..3, 512 floats each
    int sc  = blockIdx.y;     // 0..NSPLIT-1
    int b   = blockIdx.z;
    int tid = threadIdx.x;    // 0..127

    __shared__ float ws[SCHUNK];
    #pragma unroll
    for (int k = 0; k < SCHUNK / 128; k++)
        ws[tid + k * 128] = wts[b * NS + sc * SCHUNK + tid + k * 128];
    __syncthreads();

    const float4* p = (const float4*)(cs + ((size_t)(b * NS + sc * SCHUNK)) * ND
                                         + dt * 512) + tid;
    float4 acc = make_float4(0.f, 0.f, 0.f, 0.f);
    #pragma unroll 8
    for (int s = 0; s < SCHUNK; s++) {
        float w  = ws[s];
        float4 v = __ldcs(p + (size_t)s * (ND / 4));
        acc.x = fmaf(w, v.x, acc.x);
        acc.y = fmaf(w, v.y, acc.y);
        acc.z = fmaf(w, v.z, acc.z);
        acc.w = fmaf(w, v.w, acc.w);
    }
    float* dst = g_partial + ((size_t)(sc * NB + b)) * ND + dt * 512 + tid * 4;
    *(float4*)dst = acc;
}

// ---------------------------------------------------------------------------
// Kernel E: deterministic float4 reduction of the NSPLIT partials into d_out
// 16384 threads, each produces one float4 of the output
// ---------------------------------------------------------------------------
__global__ void out_reduce_kernel(float* __restrict__ out)
{
    int i = blockIdx.x * blockDim.x + threadIdx.x;  // 0..NB*ND/4-1
    const float4* p = (const float4*)g_partial + i;
    float4 a = make_float4(0.f, 0.f, 0.f, 0.f);
    #pragma unroll
    for (int c = 0; c < NSPLIT; c++) {
        float4 v = p[(size_t)c * (NB * ND / 4)];
        a.x += v.x; a.y += v.y; a.z += v.z; a.w += v.w;
    }
    ((float4*)out)[i] = a;
}

// ---------------------------------------------------------------------------
extern "C" void kernel_launch(void* const* d_in, const int* in_sizes, int n_in,
                              void* d_out, int out_size)
{
    const float* x  = (const float*)d_in[0];   // (32, 2048)
    const float* cs = (const float*)d_in[1];   // (32, 4096, 2048)
    const float* t  = (const float*)d_in[2];   // (32,)
    const float* wq = (const float*)d_in[3];   // (128,)
    const float* bq = (const float*)d_in[4];   // (128,)
    const float* wk = (const float*)d_in[5];   // (128,)
    const float* bk = (const float*)d_in[6];   // (128,)

    float* out_main = (float*)d_out;            // (32, 2048)
    float* out_wts  = out_main + NB * ND;       // (32, 4096)

    dim3 gS(NS / 64, NB);
    scores_kernel<<<gS, 256>>>(cs, x, t, wq, bq, wk, bk);

    softmax_kernel<<<NB, 512>>>(out_wts);

    dim3 gO(4, NSPLIT, NB);
    out_partial_kernel<<<gO, 128>>>(cs, out_wts);

    out_reduce_kernel<<<(NB * ND / 4) / 128, 128>>>(out_main);
}